// round 17
// baseline (speedup 1.0000x reference)
#include <cuda_runtime.h>
#include <cuda_bf16.h>
#include <cuda_fp16.h>
#include <cstdint>

#define BB 2
#define SS 2048
#define DD 1024
#define HH 16
#define MM (BB*SS)             // 4096

// GEMM tiling: 128x256 tile, K-chunk 32 (64B rows), merged Karatsuba acc
#define TM 128
#define TN 256
#define KC 32
#define NCH (DD/KC)            // 32
#define NSTAGE 3
#define OFF_AH 0               // 128 rows x 64B = 8192
#define OFF_AU 8192
#define OFF_BH 16384           // 256 rows x 64B = 16384
#define OFF_BU 32768
#define STAGE_BYTES 49152
#define GEMM_SMEM (NSTAGE*STAGE_BYTES)   // 147456 -> 1 CTA/SM

// main-term coefficient (1 - 2^-6), folded into the weight H buffers
#define C_MAIN 0.984375f

// Attention tiling (unchanged from R15)
#define QSTRIDE 68
#define KSTRIDE 68
#define SST 132
#define ATT2_SMEM ((64*QSTRIDE + 128*KSTRIDE + 128*KSTRIDE + 64)*4)

// ---------------------------------------------------------------------------
// Scratch (device globals: allocation-free rule)
// ---------------------------------------------------------------------------
__device__ float g_Q[(size_t)MM * DD];
__device__ float g_K[(size_t)MM * DD];
__device__ float g_V[(size_t)MM * DD];
__device__ __half g_Ah[(size_t)MM * DD];
__device__ __half g_Au[(size_t)MM * DD];
__device__ __half g_Wh[(size_t)4 * DD * DD];   // wq,wk,wv,wo (H pre-scaled)
__device__ __half g_Wu[(size_t)4 * DD * DD];
__device__ __half g_Ch[(size_t)MM * DD];
__device__ __half g_Cu[(size_t)MM * DD];

// ---------------------------------------------------------------------------
// Helpers
// ---------------------------------------------------------------------------
__device__ __forceinline__ uint32_t smem_u32(const void* p) {
    uint32_t a;
    asm("{ .reg .u64 t; cvta.to.shared.u64 t, %1; cvt.u32.u64 %0, t; }"
        : "=r"(a) : "l"(p));
    return a;
}

__device__ __forceinline__ void cpasync16(uint32_t dst, const void* src) {
    asm volatile("cp.async.cg.shared.global [%0], [%1], 16;"
                 :: "r"(dst), "l"(src));
}
#define CP_COMMIT() asm volatile("cp.async.commit_group;" ::: "memory")
#define CP_WAIT1()  asm volatile("cp.async.wait_group 1;" ::: "memory")
#define CP_WAIT0()  asm volatile("cp.async.wait_group 0;" ::: "memory")

__device__ __forceinline__ void ldm4(uint32_t* r, uint32_t addr) {
    asm volatile("ldmatrix.sync.aligned.m8n8.x4.shared.b16 {%0,%1,%2,%3}, [%4];"
                 : "=r"(r[0]), "=r"(r[1]), "=r"(r[2]), "=r"(r[3]) : "r"(addr));
}

__device__ __forceinline__ void mma_f32(float* c, const uint32_t* a,
                                        uint32_t b0, uint32_t b1) {
    asm volatile(
        "mma.sync.aligned.m16n8k16.row.col.f32.f16.f16.f32 "
        "{%0,%1,%2,%3}, {%4,%5,%6,%7}, {%8,%9}, {%0,%1,%2,%3};"
        : "+f"(c[0]), "+f"(c[1]), "+f"(c[2]), "+f"(c[3])
        : "r"(a[0]), "r"(a[1]), "r"(a[2]), "r"(a[3]), "r"(b0), "r"(b1));
}

// activation split: H exact, U = fp16(2^-3*H + 2^3*(x-H))
__device__ __forceinline__ void ksplit(float x, __half& h, __half& u) {
    h = __float2half_rn(x);
    const float hf = __half2float(h);
    u = __float2half_rn(fmaf(0.125f, hf, 8.0f * (x - hf)));
}

// ---------------------------------------------------------------------------
// Split pass: q (exact H) + 4 weights (H pre-scaled by C_MAIN) -> fp16 H / U
// ---------------------------------------------------------------------------
__global__ void __launch_bounds__(256) split_kernel(const float* __restrict__ q,
                                                    const float* __restrict__ wq,
                                                    const float* __restrict__ wk,
                                                    const float* __restrict__ wv,
                                                    const float* __restrict__ wo)
{
    const size_t i4 = (size_t)blockIdx.x * 256 + threadIdx.x;
    const float* src;
    __half *dh, *du;
    size_t e;
    bool wscale;
    if (i4 < 1048576) {
        src = q; e = i4;
        dh = g_Ah; du = g_Au;
        wscale = false;
    } else {
        const size_t r = i4 - 1048576;
        const int w = (int)(r >> 18);
        e = r & 262143;
        src = (w == 0) ? wq : (w == 1) ? wk : (w == 2) ? wv : wo;
        dh = g_Wh + (size_t)w * DD * DD;
        du = g_Wu + (size_t)w * DD * DD;
        wscale = true;
    }
    const float4 v = ((const float4*)src)[e];
    const float xs[4] = { v.x, v.y, v.z, v.w };
    __half hs[4], us[4];
#pragma unroll
    for (int k = 0; k < 4; ++k) {
        __half h, u;
        ksplit(xs[k], h, u);              // U built from EXACT H
        us[k] = u;
        hs[k] = wscale ? __float2half_rn(C_MAIN * __half2float(h)) : h;
    }
    *(ushort4*)(dh + e * 4) = make_ushort4(*(unsigned short*)&hs[0], *(unsigned short*)&hs[1],
                                           *(unsigned short*)&hs[2], *(unsigned short*)&hs[3]);
    *(ushort4*)(du + e * 4) = make_ushort4(*(unsigned short*)&us[0], *(unsigned short*)&us[1],
                                           *(unsigned short*)&us[2], *(unsigned short*)&us[3]);
}

// ---------------------------------------------------------------------------
// fp16 merged-Karatsuba GEMM: C = Sum(Ah*W~h) + Sum(Au*Wu)  (+bias)
//   Tile 128x256, 256 thr, 8 warps (2M x 4N), warp subtile 64x64.
//   KC=32, 3-stage cp.async; single accumulator set (scale folded into W~h).
// ---------------------------------------------------------------------------
__device__ __forceinline__ void gemm_body(const __half* __restrict__ Ah,
                                          const __half* __restrict__ Au,
                                          const __half* __restrict__ Wh,
                                          const __half* __restrict__ Wu,
                                          float* __restrict__ C,
                                          const float* __restrict__ bias)
{
    extern __shared__ char dsm[];
    const uint32_t sb = smem_u32(dsm);
    const int tid  = threadIdx.x;
    const int wid  = tid >> 5;
    const int lane = tid & 31;
    const int wm   = wid >> 2;        // 0..1 (64 rows each)
    const int wn   = wid & 3;         // 0..3 (64 cols each)
    const int brow = blockIdx.y * TM;
    const int bcol = blockIdx.x * TN;

    const __half* A0 = Ah + (size_t)brow * DD;
    const __half* A1 = Au + (size_t)brow * DD;
    const __half* B0 = Wh + (size_t)bcol * DD;
    const __half* B1 = Wu + (size_t)bcol * DD;

    float acc[4][8][4];
#pragma unroll
    for (int a = 0; a < 4; ++a)
#pragma unroll
        for (int b = 0; b < 8; ++b)
#pragma unroll
            for (int c = 0; c < 4; ++c) acc[a][b][c] = 0.f;

    auto issue = [&](int kc, int stg) {
        const uint32_t base = sb + stg * STAGE_BYTES;
        // A tiles: 128 rows x 4 c-slots = 512 slots each
#pragma unroll
        for (int it = 0; it < 2; ++it) {
            const int id = tid + it * 256;
            const int r = id >> 2, c = id & 3;
            const uint32_t sw = r * 64 + ((c ^ ((r >> 1) & 3)) << 4);
            const size_t go = (size_t)r * DD + kc * KC + c * 8;
            cpasync16(base + OFF_AH + sw, A0 + go);
            cpasync16(base + OFF_AU + sw, A1 + go);
        }
        // B tiles: 256 rows x 4 c-slots = 1024 slots each
#pragma unroll
        for (int it = 0; it < 4; ++it) {
            const int id = tid + it * 256;
            const int r = id >> 2, c = id & 3;
            const uint32_t sw = r * 64 + ((c ^ ((r >> 1) & 3)) << 4);
            const size_t go = (size_t)r * DD + kc * KC + c * 8;
            cpasync16(base + OFF_BH + sw, B0 + go);
            cpasync16(base + OFF_BU + sw, B1 + go);
        }
        CP_COMMIT();
    };

    issue(0, 0);
    issue(1, 1);

    for (int kc = 0; kc < NCH; ++kc) {
        if (kc + 1 < NCH) CP_WAIT1(); else CP_WAIT0();
        __syncthreads();
        if (kc + 2 < NCH) issue(kc + 2, (kc + 2) % NSTAGE);

        const uint32_t st = sb + (kc % NSTAGE) * STAGE_BYTES;
#pragma unroll
        for (int kk = 0; kk < 2; ++kk) {           // 2 x k16 per chunk
            const int c16 = kk * 2 + (lane >> 4);  // 16B chunk 0..3
            uint32_t aoff[4], boff[4];
#pragma unroll
            for (int mi = 0; mi < 4; ++mi) {
                const int row = wm * 64 + mi * 16 + (lane & 15);
                aoff[mi] = row * 64 + ((c16 ^ ((row >> 1) & 3)) << 4);
            }
#pragma unroll
            for (int nb = 0; nb < 4; ++nb) {
                const int row = wn * 64 + nb * 16 + (lane & 15);
                boff[nb] = row * 64 + ((c16 ^ ((row >> 1) & 3)) << 4);
            }
            // main term (pre-scaled W~h): 4+4 LDSM -> 32 MMAs
            {
                uint32_t ah[4][4], bh[4][4];
#pragma unroll
                for (int mi = 0; mi < 4; ++mi) ldm4(ah[mi], st + OFF_AH + aoff[mi]);
#pragma unroll
                for (int nb = 0; nb < 4; ++nb) ldm4(bh[nb], st + OFF_BH + boff[nb]);
#pragma unroll
                for (int mi = 0; mi < 4; ++mi)
#pragma unroll
                    for (int ni = 0; ni < 8; ++ni) {
                        const int nb = ni >> 1, sidx = ni & 1;
                        mma_f32(acc[mi][ni], ah[mi], bh[nb][sidx], bh[nb][sidx + 2]);
                    }
            }
            // correction term: 4+4 LDSM -> 32 MMAs, same accumulators
            {
                uint32_t au[4][4], bu[4][4];
#pragma unroll
                for (int mi = 0; mi < 4; ++mi) ldm4(au[mi], st + OFF_AU + aoff[mi]);
#pragma unroll
                for (int nb = 0; nb < 4; ++nb) ldm4(bu[nb], st + OFF_BU + boff[nb]);
#pragma unroll
                for (int mi = 0; mi < 4; ++mi)
#pragma unroll
                    for (int ni = 0; ni < 8; ++ni) {
                        const int nb = ni >> 1, sidx = ni & 1;
                        mma_f32(acc[mi][ni], au[mi], bu[nb][sidx], bu[nb][sidx + 2]);
                    }
            }
        }
    }

    // Epilogue (no combine — scale folded into operands)
#pragma unroll
    for (int mi = 0; mi < 4; ++mi) {
        const int row = brow + wm * 64 + mi * 16 + (lane >> 2);
#pragma unroll
        for (int ni = 0; ni < 8; ++ni) {
            const int col = bcol + wn * 64 + ni * 8 + (lane & 3) * 2;
            float2 v0 = make_float2(acc[mi][ni][0], acc[mi][ni][1]);
            float2 v1 = make_float2(acc[mi][ni][2], acc[mi][ni][3]);
            if (bias) {
                const float b0 = bias[col], b1 = bias[col + 1];
                v0.x += b0; v0.y += b1; v1.x += b0; v1.y += b1;
            }
            *(float2*)&C[(size_t)row * DD + col]       = v0;
            *(float2*)&C[(size_t)(row + 8) * DD + col] = v1;
        }
    }
}

__global__ void __launch_bounds__(256, 1) qkv_bf()
{
    const int z = blockIdx.z;
    float* Cc = (z == 0) ? g_Q : ((z == 1) ? g_K : g_V);
    gemm_body(g_Ah, g_Au,
              g_Wh + (size_t)z * DD * DD, g_Wu + (size_t)z * DD * DD,
              Cc, nullptr);
}

__global__ void __launch_bounds__(256, 1) out_bf(const float* __restrict__ bo,
                                                 float* __restrict__ out)
{
    gemm_body(g_Ch, g_Cu,
              g_Wh + (size_t)3 * DD * DD, g_Wu + (size_t)3 * DD * DD,
              out, bo);
}

// ---------------------------------------------------------------------------
// Attention v5 (unchanged from R15): trimmed softmax, deferred normalize.
// ---------------------------------------------------------------------------
__global__ void __launch_bounds__(256) attn_v5(float* __restrict__ attn_out)
{
    extern __shared__ float s[];
    float* Qs   = s;
    float* Ks   = s + 64 * QSTRIDE;
    float* Vs   = Ks + 128 * KSTRIDE;
    float* sinv = Vs + 128 * KSTRIDE;
    float* Ss   = Ks;

    const int tid  = threadIdx.x;
    const int warp = tid >> 5;
    const int lane = tid & 31;
    const int q0   = blockIdx.x * 64;
    const int bh   = blockIdx.y;
    const int h    = bh & (HH - 1);
    const int b    = bh >> 4;
    const int jbase = q0 - 32;

    const float* Qg = g_Q + ((size_t)(b * SS + q0)) * DD + h * 64;
    const float* Kg = g_K + (size_t)b * SS * DD + h * 64;
    const float* Vg = g_V + (size_t)b * SS * DD + h * 64;

    for (int idx = tid; idx < 64 * 16; idx += 256) {
        const int r = idx >> 4, c = idx & 15;
        *(float4*)&Qs[r * QSTRIDE + c * 4] = *(const float4*)&Qg[(size_t)r * DD + c * 4];
    }
    for (int idx = tid; idx < 128 * 16; idx += 256) {
        const int r = idx >> 4, c = idx & 15;
        const int j = jbase + r;
        if (j >= 0 && j < SS) {
            *(float4*)&Ks[r * KSTRIDE + c * 4] = *(const float4*)&Kg[(size_t)j * DD + c * 4];
            *(float4*)&Vs[r * KSTRIDE + c * 4] = *(const float4*)&Vg[(size_t)j * DD + c * 4];
        } else {
            *(float4*)&Vs[r * KSTRIDE + c * 4] = make_float4(0.f, 0.f, 0.f, 0.f);
        }
    }
    __syncthreads();

    const int tq = lane >> 2;
    const int tk = lane & 3;
    float sacc[8][4];
#pragma unroll
    for (int i = 0; i < 8; ++i)
#pragma unroll
        for (int j = 0; j < 4; ++j) sacc[i][j] = 0.f;

    {
        const float4* Qp = (const float4*)(Qs + tq * QSTRIDE);
        const float4* Kp = (const float4*)(Ks + (16 * warp + tk) * KSTRIDE);
#pragma unroll
        for (int d4 = 0; d4 < 16; ++d4) {
            float4 qv[8], kv[4];
#pragma unroll
            for (int i = 0; i < 8; ++i) qv[i] = Qp[i * 136 + d4];
#pragma unroll
            for (int j = 0; j < 4; ++j) kv[j] = Kp[j * 68 + d4];
#pragma unroll
            for (int i = 0; i < 8; ++i)
#pragma unroll
                for (int j = 0; j < 4; ++j) {
                    sacc[i][j] = fmaf(qv[i].x, kv[j].x, sacc[i][j]);
                    sacc[i][j] = fmaf(qv[i].y, kv[j].y, sacc[i][j]);
                    sacc[i][j] = fmaf(qv[i].z, kv[j].z, sacc[i][j]);
                    sacc[i][j] = fmaf(qv[i].w, kv[j].w, sacc[i][j]);
                }
        }
    }
    __syncthreads();

#pragma unroll
    for (int i = 0; i < 8; ++i) {
        const int qrow = tq + 8 * i;
#pragma unroll
        for (int j = 0; j < 4; ++j) {
            const int kcol = 16 * warp + tk + 4 * j;
            const int jg = jbase + kcol;
            const bool val = (jg >= 0) && (jg < SS) &&
                             (kcol >= qrow) && (kcol <= qrow + 64);
            Ss[qrow * SST + kcol] = val ? sacc[i][j] * 0.125f : 0.f;
        }
    }
    __syncthreads();

    {
        const int r = tid >> 2, p = tid & 3;
        const int ig = q0 + r;
        const int jlo = max(0, ig - 32), jhi = min(SS - 1, ig + 32);
        const int rb = jlo - jbase, n = jhi - jlo + 1;
        const int c4lo = (rb - p + 3) >> 2;
        const int c4hi = (rb + n - 1 - p) >> 2;
        float* Sr = Ss + r * SST;

        float m = -1e30f;
        for (int c4 = c4lo; c4 <= c4hi; ++c4) m = fmaxf(m, Sr[p + 4 * c4]);
        m = fmaxf(m, __shfl_xor_sync(0xffffffffu, m, 1));
        m = fmaxf(m, __shfl_xor_sync(0xffffffffu, m, 2));

        float sum = 0.f;
        for (int c4 = c4lo; c4 <= c4hi; ++c4) {
            const int c = p + 4 * c4;
            const float e = __expf(Sr[c] - m);
            Sr[c] = e;
            sum += e;
        }
        sum += __shfl_xor_sync(0xffffffffu, sum, 1);
        sum += __shfl_xor_sync(0xffffffffu, sum, 2);
        const float inv = 1.f / sum;
        if (p == 0) sinv[r] = inv;

        if (attn_out) {
            float* rowp = attn_out + ((size_t)bh * SS + ig) * SS;
            for (int c4 = c4lo; c4 <= c4hi; ++c4) {
                const int c = p + 4 * c4;
                rowp[jbase + c] = Sr[c] * inv;
            }
        }
    }
    __syncthreads();

    {
        const int qp   = lane >> 3;
        const int dgrp = lane & 7;
        const int qa   = 8 * warp + 2 * qp;
        const float4* P0 = (const float4*)(Ss + qa * SST);
        const float4* P1 = (const float4*)(Ss + (qa + 1) * SST);
        const float* Vbase = Vs + 8 * dgrp;

        float ca[8], cb[8];
#pragma unroll
        for (int i = 0; i < 8; ++i) { ca[i] = 0.f; cb[i] = 0.f; }

#pragma unroll 4
        for (int k4 = 0; k4 < 32; ++k4) {
            const float4 pa4 = P0[k4];
            const float4 pb4 = P1[k4];
            const float pa[4] = { pa4.x, pa4.y, pa4.z, pa4.w };
            const float pb[4] = { pb4.x, pb4.y, pb4.z, pb4.w };
#pragma unroll
            for (int kk = 0; kk < 4; ++kk) {
                const float* Vr = Vbase + (k4 * 4 + kk) * KSTRIDE;
                const float4 v0 = *(const float4*)&Vr[0];
                const float4 v1 = *(const float4*)&Vr[4];
                ca[0] = fmaf(pa[kk], v0.x, ca[0]); cb[0] = fmaf(pb[kk], v0.x, cb[0]);
                ca[1] = fmaf(pa[kk], v0.y, ca[1]); cb[1] = fmaf(pb[kk], v0.y, cb[1]);
                ca[2] = fmaf(pa[kk], v0.z, ca[2]); cb[2] = fmaf(pb[kk], v0.z, cb[2]);
                ca[3] = fmaf(pa[kk], v0.w, ca[3]); cb[3] = fmaf(pb[kk], v0.w, cb[3]);
                ca[4] = fmaf(pa[kk], v1.x, ca[4]); cb[4] = fmaf(pb[kk], v1.x, cb[4]);
                ca[5] = fmaf(pa[kk], v1.y, ca[5]); cb[5] = fmaf(pb[kk], v1.y, cb[5]);
                ca[6] = fmaf(pa[kk], v1.z, ca[6]); cb[6] = fmaf(pb[kk], v1.z, cb[6]);
                ca[7] = fmaf(pa[kk], v1.w, ca[7]); cb[7] = fmaf(pb[kk], v1.w, cb[7]);
            }
        }

        const float ia = sinv[qa];
        const float ib = sinv[qa + 1];
#pragma unroll
        for (int i = 0; i < 8; ++i) { ca[i] *= ia; cb[i] *= ib; }

        const size_t coa = ((size_t)(b * SS + q0 + qa)) * DD + h * 64 + 8 * dgrp;
        const size_t cob = coa + DD;
        __half hh[8], uu[8];
#pragma unroll
        for (int e = 0; e < 8; ++e) ksplit(ca[e], hh[e], uu[e]);
        *(ushort4*)(g_Ch + coa)     = make_ushort4(*(unsigned short*)&hh[0], *(unsigned short*)&hh[1],
                                                   *(unsigned short*)&hh[2], *(unsigned short*)&hh[3]);
        *(ushort4*)(g_Ch + coa + 4) = make_ushort4(*(unsigned short*)&hh[4], *(unsigned short*)&hh[5],
                                                   *(unsigned short*)&hh[6], *(unsigned short*)&hh[7]);
        *(ushort4*)(g_Cu + coa)     = make_ushort4(*(unsigned short*)&uu[0], *(unsigned short*)&uu[1],
                                                   *(unsigned short*)&uu[2], *(unsigned short*)&uu[3]);
        *(ushort4*)(g_Cu + coa + 4) = make_ushort4(*(unsigned short*)&uu[4], *(unsigned short*)&uu[5],
                                                   *(unsigned short*)&uu[6], *(unsigned short*)&uu[7]);
#pragma unroll
        for (int e = 0; e < 8; ++e) ksplit(cb[e], hh[e], uu[e]);
        *(ushort4*)(g_Ch + cob)     = make_ushort4(*(unsigned short*)&hh[0], *(unsigned short*)&hh[1],
                                                   *(unsigned short*)&hh[2], *(unsigned short*)&hh[3]);
        *(ushort4*)(g_Ch + cob + 4) = make_ushort4(*(unsigned short*)&hh[4], *(unsigned short*)&hh[5],
                                                   *(unsigned short*)&hh[6], *(unsigned short*)&hh[7]);
        *(ushort4*)(g_Cu + cob)     = make_ushort4(*(unsigned short*)&uu[0], *(unsigned short*)&uu[1],
                                                   *(unsigned short*)&uu[2], *(unsigned short*)&uu[3]);
        *(ushort4*)(g_Cu + cob + 4) = make_ushort4(*(unsigned short*)&uu[4], *(unsigned short*)&uu[5],
                                                   *(unsigned short*)&uu[6], *(unsigned short*)&uu[7]);
    }
}

// ---------------------------------------------------------------------------
extern "C" void kernel_launch(void* const* d_in, const int* in_sizes, int n_in,
                              void* d_out, int out_size)
{
    const float* q  = (const float*)d_in[0];
    const float* wq = (const float*)d_in[1];
    const float* wk = (const float*)d_in[2];
    const float* wv = (const float*)d_in[3];
    const float* wo = (const float*)d_in[4];
    const float* bo = (const float*)d_in[5];
    float* out = (float*)d_out;

    const size_t out_elems  = (size_t)BB * SS * DD;
    const bool   write_attn = (size_t)out_size > out_elems;
    float* attn = out + out_elems;

    static cudaStream_t s2 = nullptr;
    static cudaEvent_t evF = nullptr, evJ = nullptr;
    if (!s2) {
        cudaStreamCreateWithFlags(&s2, cudaStreamNonBlocking);
        cudaEventCreateWithFlags(&evF, cudaEventDisableTiming);
        cudaEventCreateWithFlags(&evJ, cudaEventDisableTiming);
        cudaFuncSetAttribute(qkv_bf,  cudaFuncAttributeMaxDynamicSharedMemorySize, GEMM_SMEM);
        cudaFuncSetAttribute(out_bf,  cudaFuncAttributeMaxDynamicSharedMemorySize, GEMM_SMEM);
        cudaFuncSetAttribute(attn_v5, cudaFuncAttributeMaxDynamicSharedMemorySize, ATT2_SMEM);
    }

    if (write_attn) {
        // R12-best arrangement: memset on side stream overlapped with
        // split+qkv, joined before the attn band scatter.
        cudaEventRecord(evF, 0);
        cudaStreamWaitEvent(s2, evF, 0);
        cudaMemsetAsync(attn, 0, (size_t)BB * HH * SS * SS * sizeof(float), s2);
        cudaEventRecord(evJ, s2);
    }

    // 1) split q + weights into fp16 H / U (weight H pre-scaled)
    split_kernel<<<8192, 256>>>(q, wq, wk, wv, wo);

    // 2) QKV projections (merged-acc Karatsuba, 128x256 tiles)
    dim3 gq3(DD / TN, MM / TM, 3);
    qkv_bf<<<gq3, 256, GEMM_SMEM>>>();

    if (write_attn) cudaStreamWaitEvent(0, evJ, 0);

    // 3) register-tiled local attention
    dim3 ga(SS / 64, BB * HH);
    attn_v5<<<ga, 256, ATT2_SMEM>>>(write_attn ? attn : nullptr);

    // 4) output projection + bias
    dim3 go(DD / TN, MM / TM, 1);
    out_bf<<<go, 256, GEMM_SMEM>>>(bo, out);
}